// round 1
// baseline (speedup 1.0000x reference)
#include <cuda_runtime.h>
#include <cstdint>

#define N_NODES 50000
#define N_EDGES 800000
#define H 128

// Scratch (allocation-free rule: __device__ globals)
__device__ __align__(16) float g_agg_msg[(size_t)N_NODES * H];
__device__ __align__(16) float g_agg_coord[(size_t)N_NODES * 3];
__device__ __align__(16) float g_count[N_NODES];

__device__ __forceinline__ float silu_f(float v) {
    return v * (1.0f / (1.0f + __expf(-v)));
}

// Tiled GEMM step: acc[4][8] += As(64x128, row-major smem) @ Wg(128x128, global row-major)
// Block: 256 threads, tn = tid&15 (8 cols each), tm = tid>>4 (4 rows each).
__device__ __forceinline__ void gemm128(const float* __restrict__ As,
                                        const float* __restrict__ Wg,
                                        float* sW,
                                        float acc[4][8],
                                        int tm, int tn, int tid)
{
    for (int kt = 0; kt < 128; kt += 16) {
        __syncthreads();  // protect sW from previous chunk's readers
        const float4* Wv = (const float4*)(Wg + (size_t)kt * H);
        float4* sWv = (float4*)sW;
        sWv[tid]       = Wv[tid];
        sWv[tid + 256] = Wv[tid + 256];
        __syncthreads();
#pragma unroll
        for (int kk = 0; kk < 16; kk++) {
            float a[4];
#pragma unroll
            for (int m = 0; m < 4; m++) a[m] = As[(tm * 4 + m) * H + kt + kk];
            float4 w0 = *(const float4*)&sW[kk * H + tn * 8];
            float4 w1 = *(const float4*)&sW[kk * H + tn * 8 + 4];
#pragma unroll
            for (int m = 0; m < 4; m++) {
                acc[m][0] += a[m] * w0.x; acc[m][1] += a[m] * w0.y;
                acc[m][2] += a[m] * w0.z; acc[m][3] += a[m] * w0.w;
                acc[m][4] += a[m] * w1.x; acc[m][5] += a[m] * w1.y;
                acc[m][6] += a[m] * w1.z; acc[m][7] += a[m] * w1.w;
            }
        }
    }
}

__device__ __forceinline__ void init_bias(float acc[4][8], const float* __restrict__ bias, int tn)
{
    float4 b0 = *(const float4*)(bias + tn * 8);
    float4 b1 = *(const float4*)(bias + tn * 8 + 4);
#pragma unroll
    for (int m = 0; m < 4; m++) {
        acc[m][0] = b0.x; acc[m][1] = b0.y; acc[m][2] = b0.z; acc[m][3] = b0.w;
        acc[m][4] = b1.x; acc[m][5] = b1.y; acc[m][6] = b1.z; acc[m][7] = b1.w;
    }
}

__device__ __forceinline__ void apply_silu(float acc[4][8])
{
#pragma unroll
    for (int m = 0; m < 4; m++)
#pragma unroll
        for (int n = 0; n < 8; n++)
            acc[m][n] = silu_f(acc[m][n]);
}

__device__ __forceinline__ void store_act(float* dst, const float acc[4][8], int tm, int tn)
{
#pragma unroll
    for (int m = 0; m < 4; m++) {
        int row = tm * 4 + m;
        float4 v0 = make_float4(acc[m][0], acc[m][1], acc[m][2], acc[m][3]);
        float4 v1 = make_float4(acc[m][4], acc[m][5], acc[m][6], acc[m][7]);
        *(float4*)&dst[row * H + tn * 8]     = v0;
        *(float4*)&dst[row * H + tn * 8 + 4] = v1;
    }
}

// ---------------------------------------------------------------------------
// Zero scratch
// ---------------------------------------------------------------------------
__global__ void zero_kernel()
{
    int i = blockIdx.x * blockDim.x + threadIdx.x;
    if (i < N_NODES * H) g_agg_msg[i] = 0.0f;
    if (i < N_NODES * 3) g_agg_coord[i] = 0.0f;
    if (i < N_NODES)     g_count[i] = 0.0f;
}

// ---------------------------------------------------------------------------
// Fused edge kernel: 64 edges per block.
//   msg = silu(silu([h_s|h_d|ea|d2] @ W1 + b1) @ W2 + b2)
//   cw  = silu(msg @ Wc1 + bc1) @ Wc2 + bc2
//   atomics: agg_msg += msg, agg_coord += rel*cw, count += 1
// ---------------------------------------------------------------------------
__global__ __launch_bounds__(256, 2) void edge_kernel(
    const float* __restrict__ h,   const float* __restrict__ x,
    const int*   __restrict__ ei,  const float* __restrict__ ea,
    const float* __restrict__ W1,  const float* __restrict__ b1,
    const float* __restrict__ W2,  const float* __restrict__ b2,
    const float* __restrict__ Wc1, const float* __restrict__ bc1,
    const float* __restrict__ Wc2, const float* __restrict__ bc2)
{
    extern __shared__ float smem[];
    float* sA   = smem;               // 64*128  (h_src, later hidden1)
    float* sB   = sA + 64 * H;        // 64*128  (h_dst, later msg)
    float* sW   = sB + 64 * H;        // 16*128
    float* sRel = sW + 16 * H;        // 64*3
    float* sEa  = sRel + 64 * 3;      // 64*3
    float* sDsq = sEa + 64 * 3;       // 64
    int*   sSrc = (int*)(sDsq + 64);  // 64
    int*   sDst = sSrc + 64;          // 64

    int tid = threadIdx.x;
    int tn = tid & 15;
    int tm = tid >> 4;
    int ebase = blockIdx.x * 64;

    if (tid < 64) {
        int e = ebase + tid;
        int s = ei[e];
        int d = ei[N_EDGES + e];
        sSrc[tid] = s;
        sDst[tid] = d;
        float rx = x[s * 3 + 0] - x[d * 3 + 0];
        float ry = x[s * 3 + 1] - x[d * 3 + 1];
        float rz = x[s * 3 + 2] - x[d * 3 + 2];
        sRel[tid * 3 + 0] = rx; sRel[tid * 3 + 1] = ry; sRel[tid * 3 + 2] = rz;
        sDsq[tid] = rx * rx + ry * ry + rz * rz;
        sEa[tid * 3 + 0] = ea[e * 3 + 0];
        sEa[tid * 3 + 1] = ea[e * 3 + 1];
        sEa[tid * 3 + 2] = ea[e * 3 + 2];
    }
    __syncthreads();

    // gather h[src] -> sA, h[dst] -> sB (vectorized, coalesced along cols)
    {
        const float4* hv = (const float4*)h;
        float4* sA4 = (float4*)sA;
        float4* sB4 = (float4*)sB;
#pragma unroll
        for (int j = 0; j < 8; j++) {
            int idx = tid + j * 256;          // 0..2047
            int row = idx >> 5;
            int c4  = idx & 31;
            sA4[idx] = hv[(size_t)sSrc[row] * 32 + c4];
            sB4[idx] = hv[(size_t)sDst[row] * 32 + c4];
        }
    }

    float acc[4][8];

    // ---- stage 1: msg_in @ W1 + b1, K = 260 ----
    init_bias(acc, b1, tn);
    gemm128(sA, W1, sW, acc, tm, tn, tid);            // k in [0,128)   : h_src
    gemm128(sB, W1 + 128 * H, sW, acc, tm, tn, tid);  // k in [128,256) : h_dst
    // tail k = 256..259 : edge_attr(3), dist_sq(1)
    __syncthreads();
    if (tid < 128) ((float4*)sW)[tid] = ((const float4*)(W1 + 256 * H))[tid];
    __syncthreads();
#pragma unroll
    for (int m = 0; m < 4; m++) {
        int row = tm * 4 + m;
        float av[4] = { sEa[row * 3 + 0], sEa[row * 3 + 1], sEa[row * 3 + 2], sDsq[row] };
#pragma unroll
        for (int kk = 0; kk < 4; kk++) {
            float4 w0 = *(const float4*)&sW[kk * H + tn * 8];
            float4 w1 = *(const float4*)&sW[kk * H + tn * 8 + 4];
            acc[m][0] += av[kk] * w0.x; acc[m][1] += av[kk] * w0.y;
            acc[m][2] += av[kk] * w0.z; acc[m][3] += av[kk] * w0.w;
            acc[m][4] += av[kk] * w1.x; acc[m][5] += av[kk] * w1.y;
            acc[m][6] += av[kk] * w1.z; acc[m][7] += av[kk] * w1.w;
        }
    }
    apply_silu(acc);
    __syncthreads();
    store_act(sA, acc, tm, tn);   // hidden1 -> sA

    // ---- stage 2: msg = silu(hidden1 @ W2 + b2) ----
    init_bias(acc, b2, tn);
    gemm128(sA, W2, sW, acc, tm, tn, tid);
    apply_silu(acc);
    __syncthreads();
    store_act(sB, acc, tm, tn);   // msg -> sB

    // ---- stage 3: c1 = silu(msg @ Wc1 + bc1) ----
    init_bias(acc, bc1, tn);
    gemm128(sB, Wc1, sW, acc, tm, tn, tid);
    apply_silu(acc);

    // coord_w = c1 @ Wc2 + bc2 : per-row dot over 128, partial over this thread's 8 cols
    {
        float4 c0 = *(const float4*)(Wc2 + tn * 8);
        float4 c1v = *(const float4*)(Wc2 + tn * 8 + 4);
        float pw[4];
#pragma unroll
        for (int m = 0; m < 4; m++) {
            pw[m] = acc[m][0] * c0.x + acc[m][1] * c0.y + acc[m][2] * c0.z + acc[m][3] * c0.w
                  + acc[m][4] * c1v.x + acc[m][5] * c1v.y + acc[m][6] * c1v.z + acc[m][7] * c1v.w;
        }
#pragma unroll
        for (int off = 1; off < 16; off <<= 1) {
#pragma unroll
            for (int m = 0; m < 4; m++)
                pw[m] += __shfl_xor_sync(0xffffffffu, pw[m], off);
        }
        if (tn == 0) {
            float bcc = bc2[0];
#pragma unroll
            for (int m = 0; m < 4; m++) {
                int row = tm * 4 + m;
                int d = sDst[row];
                float w = pw[m] + bcc;
                atomicAdd(&g_agg_coord[(size_t)d * 3 + 0], sRel[row * 3 + 0] * w);
                atomicAdd(&g_agg_coord[(size_t)d * 3 + 1], sRel[row * 3 + 1] * w);
                atomicAdd(&g_agg_coord[(size_t)d * 3 + 2], sRel[row * 3 + 2] * w);
                atomicAdd(&g_count[d], 1.0f);
            }
        }
    }

    // ---- agg_msg atomics (msg is in sB) ----
#pragma unroll
    for (int m = 0; m < 4; m++) {
        int row = tm * 4 + m;
        int d = sDst[row];
        float* dp = &g_agg_msg[(size_t)d * H + tn * 8];
        float4 v0 = *(const float4*)&sB[row * H + tn * 8];
        float4 v1 = *(const float4*)&sB[row * H + tn * 8 + 4];
        atomicAdd(dp + 0, v0.x); atomicAdd(dp + 1, v0.y);
        atomicAdd(dp + 2, v0.z); atomicAdd(dp + 3, v0.w);
        atomicAdd(dp + 4, v1.x); atomicAdd(dp + 5, v1.y);
        atomicAdd(dp + 6, v1.z); atomicAdd(dp + 7, v1.w);
    }
}

// ---------------------------------------------------------------------------
// Fused node kernel: 64 nodes per block.
//   h_upd = silu([h|agg] @ Wn1 + bn1) @ Wn2 + bn2
//   h_out = LN(h + h_upd); x_out = x + agg_coord / max(count,1)
// ---------------------------------------------------------------------------
__global__ __launch_bounds__(256, 2) void node_kernel(
    const float* __restrict__ h,   const float* __restrict__ x,
    const float* __restrict__ Wn1, const float* __restrict__ bn1,
    const float* __restrict__ Wn2, const float* __restrict__ bn2,
    const float* __restrict__ gamma, const float* __restrict__ beta,
    float* __restrict__ out_h, float* __restrict__ out_x)
{
    extern __shared__ float smem[];
    float* sA = smem;            // 64*128 : h tile (kept for residual)
    float* sB = sA + 64 * H;     // 64*128 : agg -> t1 -> y
    float* sW = sB + 64 * H;     // 16*128

    int tid = threadIdx.x;
    int tn = tid & 15;
    int tm = tid >> 4;
    int nbase = blockIdx.x * 64;

    // gather h and agg_msg tiles (guard tail)
    {
        const float4* hv = (const float4*)h;
        const float4* av = (const float4*)g_agg_msg;
        float4* sA4 = (float4*)sA;
        float4* sB4 = (float4*)sB;
        float4 z = make_float4(0.f, 0.f, 0.f, 0.f);
#pragma unroll
        for (int j = 0; j < 8; j++) {
            int idx = tid + j * 256;
            int row = idx >> 5;
            int c4  = idx & 31;
            int node = nbase + row;
            if (node < N_NODES) {
                sA4[idx] = hv[(size_t)node * 32 + c4];
                sB4[idx] = av[(size_t)node * 32 + c4];
            } else {
                sA4[idx] = z; sB4[idx] = z;
            }
        }
    }

    float acc[4][8];

    // ---- t1 = silu([h|agg] @ Wn1 + bn1), K = 256 ----
    init_bias(acc, bn1, tn);
    gemm128(sA, Wn1, sW, acc, tm, tn, tid);
    gemm128(sB, Wn1 + 128 * H, sW, acc, tm, tn, tid);
    apply_silu(acc);
    __syncthreads();
    store_act(sB, acc, tm, tn);   // t1 -> sB

    // ---- h_upd = t1 @ Wn2 + bn2 ----
    init_bias(acc, bn2, tn);
    gemm128(sB, Wn2, sW, acc, tm, tn, tid);

    // y = h + h_upd -> sB
    __syncthreads();
#pragma unroll
    for (int m = 0; m < 4; m++) {
        int row = tm * 4 + m;
        float4 h0 = *(const float4*)&sA[row * H + tn * 8];
        float4 h1 = *(const float4*)&sA[row * H + tn * 8 + 4];
        float4 y0 = make_float4(h0.x + acc[m][0], h0.y + acc[m][1], h0.z + acc[m][2], h0.w + acc[m][3]);
        float4 y1 = make_float4(h1.x + acc[m][4], h1.y + acc[m][5], h1.z + acc[m][6], h1.w + acc[m][7]);
        *(float4*)&sB[row * H + tn * 8]     = y0;
        *(float4*)&sB[row * H + tn * 8 + 4] = y1;
    }
    __syncthreads();

    // ---- LayerNorm over 128 : 4 threads per row ----
    {
        int row = tid >> 2;
        int part = tid & 3;
        int node = nbase + row;
        const float4* yv = (const float4*)sB;
        float s = 0.f, sq = 0.f;
        float4 vals[8];
#pragma unroll
        for (int j = 0; j < 8; j++) {
            float4 v = yv[row * 32 + part * 8 + j];
            vals[j] = v;
            s  += v.x + v.y + v.z + v.w;
            sq += v.x * v.x + v.y * v.y + v.z * v.z + v.w * v.w;
        }
        s  += __shfl_xor_sync(0xffffffffu, s, 1);
        sq += __shfl_xor_sync(0xffffffffu, sq, 1);
        s  += __shfl_xor_sync(0xffffffffu, s, 2);
        sq += __shfl_xor_sync(0xffffffffu, sq, 2);
        float mu  = s * (1.0f / 128.0f);
        float var = sq * (1.0f / 128.0f) - mu * mu;
        float inv = rsqrtf(var + 1e-5f);
        if (node < N_NODES) {
            float4* ov = (float4*)(out_h + (size_t)node * H);
#pragma unroll
            for (int j = 0; j < 8; j++) {
                int c4 = part * 8 + j;
                float4 g = *(const float4*)(gamma + c4 * 4);
                float4 b = *(const float4*)(beta + c4 * 4);
                float4 v = vals[j];
                float4 o;
                o.x = (v.x - mu) * inv * g.x + b.x;
                o.y = (v.y - mu) * inv * g.y + b.y;
                o.z = (v.z - mu) * inv * g.z + b.z;
                o.w = (v.w - mu) * inv * g.w + b.w;
                ov[c4] = o;
            }
        }
    }

    // ---- x_out ----
    if (tid < 192) {
        int r = tid / 3, c = tid % 3;
        int node = nbase + r;
        if (node < N_NODES) {
            float cnt = fmaxf(g_count[node], 1.0f);
            out_x[(size_t)node * 3 + c] = x[(size_t)node * 3 + c]
                                        + g_agg_coord[(size_t)node * 3 + c] / cnt;
        }
    }
}

// ---------------------------------------------------------------------------
extern "C" void kernel_launch(void* const* d_in, const int* in_sizes, int n_in,
                              void* d_out, int out_size)
{
    const float* h    = (const float*)d_in[0];
    const float* x    = (const float*)d_in[1];
    const int*   eidx = (const int*)  d_in[2];
    const float* ea   = (const float*)d_in[3];
    const float* W1   = (const float*)d_in[4];
    const float* b1   = (const float*)d_in[5];
    const float* W2   = (const float*)d_in[6];
    const float* b2   = (const float*)d_in[7];
    const float* Wc1  = (const float*)d_in[8];
    const float* bc1  = (const float*)d_in[9];
    const float* Wc2  = (const float*)d_in[10];
    const float* bc2  = (const float*)d_in[11];
    const float* Wn1  = (const float*)d_in[12];
    const float* bn1  = (const float*)d_in[13];
    const float* Wn2  = (const float*)d_in[14];
    const float* bn2  = (const float*)d_in[15];
    const float* gamma = (const float*)d_in[16];
    const float* beta  = (const float*)d_in[17];

    float* out_h = (float*)d_out;
    float* out_x = out_h + (size_t)N_NODES * H;

    const int EDGE_SMEM = (64 * H + 64 * H + 16 * H + 64 * 3 + 64 * 3 + 64 + 64 + 64) * 4;
    const int NODE_SMEM = (64 * H + 64 * H + 16 * H) * 4;
    cudaFuncSetAttribute(edge_kernel, cudaFuncAttributeMaxDynamicSharedMemorySize, EDGE_SMEM);
    cudaFuncSetAttribute(node_kernel, cudaFuncAttributeMaxDynamicSharedMemorySize, NODE_SMEM);

    zero_kernel<<<(N_NODES * H + 255) / 256, 256>>>();
    edge_kernel<<<N_EDGES / 64, 256, EDGE_SMEM>>>(h, x, eidx, ea,
                                                  W1, b1, W2, b2, Wc1, bc1, Wc2, bc2);
    node_kernel<<<(N_NODES + 63) / 64, 256, NODE_SMEM>>>(h, x, Wn1, bn1, Wn2, bn2,
                                                         gamma, beta, out_h, out_x);
}